// round 1
// baseline (speedup 1.0000x reference)
#include <cuda_runtime.h>
#include <cuda_bf16.h>
#include <math.h>
#include <float.h>

// Problem constants
#define BB 4
#define SS 2048
#define DD 1024
#define HH 16
#define HD 64
#define D3 (3*DD)       // 3072
#define MTOT (BB*SS)    // 8192

// Scratch (allocation-free rule: __device__ globals)
__device__ float g_qkv[(size_t)MTOT * D3];   // [B*S, 3D]
__device__ float g_attn[(size_t)MTOT * DD];  // [B*S, D] merged-head attention output

// ---------------------------------------------------------------------------
// SGEMM with bias: C[M,N] = A[M,K] @ B[K,N] + bias[N]
// BM=BN=128, BK=8, 256 threads, 8x8 register tile per thread.
// All dims divisible (M=8192, N in {3072,1024}, K=1024) — no bounds checks.
// ---------------------------------------------------------------------------
__global__ __launch_bounds__(256, 2)
void sgemm_bias(const float* __restrict__ A, const float* __restrict__ B,
                const float* __restrict__ bias, float* __restrict__ C,
                int M, int N, int K) {
    const int BM = 128, BN = 128, BK = 8, TM = 8, TN = 8;
    __shared__ float As[BK][BM];     // A stored transposed: As[k][m]
    __shared__ float Bs[BK][BN];

    int tid  = threadIdx.x;
    int bcol = blockIdx.x;   // N tiles
    int brow = blockIdx.y;   // M tiles
    int tcol = tid & 15;     // 0..15
    int trow = tid >> 4;     // 0..15

    // gmem load mapping
    int aRow = tid >> 1;            // 0..127
    int aCol = (tid & 1) << 2;      // 0 or 4
    int bRow = tid >> 5;            // 0..7
    int bCol = (tid & 31) << 2;     // 0..124

    const float* Ablk = A + (size_t)brow * BM * K;
    const float* Bblk = B + (size_t)bcol * BN;

    float acc[TM][TN];
    #pragma unroll
    for (int i = 0; i < TM; i++)
        #pragma unroll
        for (int j = 0; j < TN; j++) acc[i][j] = 0.0f;

    for (int k0 = 0; k0 < K; k0 += BK) {
        float4 a4 = *(const float4*)(Ablk + (size_t)aRow * K + k0 + aCol);
        As[aCol + 0][aRow] = a4.x;
        As[aCol + 1][aRow] = a4.y;
        As[aCol + 2][aRow] = a4.z;
        As[aCol + 3][aRow] = a4.w;
        float4 b4 = *(const float4*)(Bblk + (size_t)(k0 + bRow) * N + bCol);
        *(float4*)&Bs[bRow][bCol] = b4;
        __syncthreads();

        #pragma unroll
        for (int kk = 0; kk < BK; kk++) {
            float ar[TM], br[TN];
            *(float4*)&ar[0] = *(const float4*)&As[kk][trow * TM];
            *(float4*)&ar[4] = *(const float4*)&As[kk][trow * TM + 4];
            *(float4*)&br[0] = *(const float4*)&Bs[kk][tcol * TN];
            *(float4*)&br[4] = *(const float4*)&Bs[kk][tcol * TN + 4];
            #pragma unroll
            for (int i = 0; i < TM; i++)
                #pragma unroll
                for (int j = 0; j < TN; j++)
                    acc[i][j] = fmaf(ar[i], br[j], acc[i][j]);
        }
        __syncthreads();
    }

    // epilogue: add bias, vectorized stores
    #pragma unroll
    for (int i = 0; i < TM; i++) {
        size_t r = (size_t)brow * BM + trow * TM + i;
        #pragma unroll
        for (int j = 0; j < TN; j += 4) {
            int c = bcol * BN + tcol * TN + j;
            float4 bv = *(const float4*)(bias + c);
            float4 o;
            o.x = acc[i][j + 0] + bv.x;
            o.y = acc[i][j + 1] + bv.y;
            o.z = acc[i][j + 2] + bv.z;
            o.w = acc[i][j + 3] + bv.w;
            *(float4*)(C + r * N + c) = o;
        }
    }
}

// ---------------------------------------------------------------------------
// Flash attention (causal), fp32. One block = (b, h, q-tile of 64 rows).
// 256 threads; thread (trow,tcol) owns 4x4 of the 64x64 score tile.
// Online-softmax row state (m, l) replicated across 16-lane groups (shfl).
// Smem tiles padded to stride 65 (scalar, conflict-free).
// ---------------------------------------------------------------------------
#define QT (SS / 64)     // 32 query tiles

__global__ __launch_bounds__(256, 3)
void flash_attn(const float* __restrict__ qkv, float* __restrict__ out) {
    extern __shared__ float sm[];
    float* Qs = sm;                 // [64][65]
    float* Ks = sm + 64 * 65;       // [64][65]
    float* Vs = sm + 2 * 64 * 65;   // [64][65]
    float* Ps = sm + 3 * 64 * 65;   // [64][65]

    int idx = blockIdx.x;
    int qt = idx % QT; idx /= QT;
    int h  = idx % HH;
    int b  = idx / HH;

    int tid  = threadIdx.x;
    int tcol = tid & 15;
    int trow = tid >> 4;
    int r0 = trow * 4;
    int c0 = tcol * 4;

    const float* qbase = qkv + (size_t)b * SS * D3 + h * HD;            // + s*D3
    const float* kbase = qbase + DD;
    const float* vbase = qbase + 2 * DD;

    // Load Q tile (scaled by 1/sqrt(HD)=0.125)
    for (int i = tid; i < 64 * 16; i += 256) {
        int r = i >> 4, c = (i & 15) << 2;
        float4 v = *(const float4*)(qbase + (size_t)(qt * 64 + r) * D3 + c);
        Qs[r * 65 + c + 0] = v.x * 0.125f;
        Qs[r * 65 + c + 1] = v.y * 0.125f;
        Qs[r * 65 + c + 2] = v.z * 0.125f;
        Qs[r * 65 + c + 3] = v.w * 0.125f;
    }

    float o[4][4];
    float m[4], l[4];
    #pragma unroll
    for (int i = 0; i < 4; i++) {
        m[i] = -FLT_MAX; l[i] = 0.0f;
        #pragma unroll
        for (int j = 0; j < 4; j++) o[i][j] = 0.0f;
    }

    for (int kt = 0; kt <= qt; kt++) {
        __syncthreads();   // previous iter's Ks/Vs/Ps fully consumed
        // load K and V tiles
        for (int i = tid; i < 64 * 16; i += 256) {
            int r = i >> 4, c = (i & 15) << 2;
            float4 kv = *(const float4*)(kbase + (size_t)(kt * 64 + r) * D3 + c);
            Ks[r * 65 + c + 0] = kv.x;
            Ks[r * 65 + c + 1] = kv.y;
            Ks[r * 65 + c + 2] = kv.z;
            Ks[r * 65 + c + 3] = kv.w;
            float4 vv = *(const float4*)(vbase + (size_t)(kt * 64 + r) * D3 + c);
            Vs[r * 65 + c + 0] = vv.x;
            Vs[r * 65 + c + 1] = vv.y;
            Vs[r * 65 + c + 2] = vv.z;
            Vs[r * 65 + c + 3] = vv.w;
        }
        __syncthreads();

        // S = Q * K^T (scale folded into Q)
        float s[4][4];
        #pragma unroll
        for (int i = 0; i < 4; i++)
            #pragma unroll
            for (int j = 0; j < 4; j++) s[i][j] = 0.0f;

        #pragma unroll 8
        for (int d = 0; d < 64; d++) {
            float qr[4], kc[4];
            #pragma unroll
            for (int i = 0; i < 4; i++) qr[i] = Qs[(r0 + i) * 65 + d];
            #pragma unroll
            for (int j = 0; j < 4; j++) kc[j] = Ks[(c0 + j) * 65 + d];
            #pragma unroll
            for (int i = 0; i < 4; i++)
                #pragma unroll
                for (int j = 0; j < 4; j++)
                    s[i][j] = fmaf(qr[i], kc[j], s[i][j]);
        }

        // causal mask on diagonal tile
        if (kt == qt) {
            #pragma unroll
            for (int i = 0; i < 4; i++)
                #pragma unroll
                for (int j = 0; j < 4; j++)
                    if (c0 + j > r0 + i) s[i][j] = -1e30f;
        }

        // online softmax update (per-row, replicated across 16-lane groups)
        float alpha[4], psum[4];
        #pragma unroll
        for (int i = 0; i < 4; i++) {
            float mt = fmaxf(fmaxf(s[i][0], s[i][1]), fmaxf(s[i][2], s[i][3]));
            #pragma unroll
            for (int off = 1; off < 16; off <<= 1)
                mt = fmaxf(mt, __shfl_xor_sync(0xffffffffu, mt, off));
            float mn = fmaxf(m[i], mt);
            alpha[i] = __expf(m[i] - mn);
            float ps = 0.0f;
            #pragma unroll
            for (int j = 0; j < 4; j++) {
                float p = __expf(s[i][j] - mn);
                Ps[(r0 + i) * 65 + c0 + j] = p;
                ps += p;
            }
            #pragma unroll
            for (int off = 1; off < 16; off <<= 1)
                ps += __shfl_xor_sync(0xffffffffu, ps, off);
            psum[i] = ps;
            m[i] = mn;
        }
        #pragma unroll
        for (int i = 0; i < 4; i++) {
            l[i] = l[i] * alpha[i] + psum[i];
            #pragma unroll
            for (int j = 0; j < 4; j++) o[i][j] *= alpha[i];
        }
        __syncthreads();   // Ps visible to all

        // O += P @ V
        #pragma unroll 8
        for (int k = 0; k < 64; k++) {
            float pr[4], vc[4];
            #pragma unroll
            for (int i = 0; i < 4; i++) pr[i] = Ps[(r0 + i) * 65 + k];
            #pragma unroll
            for (int j = 0; j < 4; j++) vc[j] = Vs[k * 65 + c0 + j];
            #pragma unroll
            for (int i = 0; i < 4; i++)
                #pragma unroll
                for (int j = 0; j < 4; j++)
                    o[i][j] = fmaf(pr[i], vc[j], o[i][j]);
        }
    }

    // normalize and write merged-head layout: out[b*S + s][h*HD + d]
    #pragma unroll
    for (int i = 0; i < 4; i++) {
        float inv = 1.0f / l[i];
        size_t row = (size_t)b * SS + qt * 64 + r0 + i;
        float* op = out + row * DD + h * HD + c0;
        float4 v;
        v.x = o[i][0] * inv;
        v.y = o[i][1] * inv;
        v.z = o[i][2] * inv;
        v.w = o[i][3] * inv;
        *(float4*)op = v;
    }
}

// ---------------------------------------------------------------------------
// Launch
// ---------------------------------------------------------------------------
extern "C" void kernel_launch(void* const* d_in, const int* in_sizes, int n_in,
                              void* d_out, int out_size) {
    const float* x        = (const float*)d_in[0];
    // d_in[1] = mask (bool causal) — known statically, unused
    const float* c_attn_w = (const float*)d_in[2];
    const float* c_attn_b = (const float*)d_in[3];
    const float* c_proj_w = (const float*)d_in[4];
    const float* c_proj_b = (const float*)d_in[5];
    float* out = (float*)d_out;

    void* qkv_ptr = nullptr;
    void* attn_ptr = nullptr;
    cudaGetSymbolAddress(&qkv_ptr, g_qkv);
    cudaGetSymbolAddress(&attn_ptr, g_attn);
    float* qkv  = (float*)qkv_ptr;
    float* attn = (float*)attn_ptr;

    const int smem_attn = 4 * 64 * 65 * sizeof(float);  // 66,560 B
    cudaFuncSetAttribute(flash_attn, cudaFuncAttributeMaxDynamicSharedMemorySize, smem_attn);

    // 1) qkv = x @ c_attn_w + b   [8192,1024]x[1024,3072]
    {
        dim3 grid(D3 / 128, MTOT / 128);
        sgemm_bias<<<grid, 256>>>(x, c_attn_w, c_attn_b, qkv, MTOT, D3, DD);
    }
    // 2) flash attention -> attn [8192,1024] merged heads
    {
        dim3 grid(BB * HH * QT);
        flash_attn<<<grid, 256, smem_attn>>>(qkv, attn);
    }
    // 3) out = attn @ c_proj_w + b   [8192,1024]x[1024,1024]
    {
        dim3 grid(DD / 128, MTOT / 128);
        sgemm_bias<<<grid, 256>>>(attn, c_proj_w, c_proj_b, out, MTOT, DD, DD);
    }
}